// round 11
// baseline (speedup 1.0000x reference)
#include <cuda_runtime.h>

// Node2VecModel: N=6, EMB=32. One latency-bound kernel, warp-specialized:
//   warps 0-5: energy MLP, FULLY warp-autonomous (no barriers, no smem):
//              warp w owns node w; x row lives in lane registers (EMB==32),
//              h1 via shuffle-broadcast, h1 kept in registers, h2 via
//              shuffle-broadcast, head via butterfly reduce.
//   warps 6-8 (bar 2): raw path logits -> gumbel-max walk -> out[6..12]
// Invariants (measured): weights in registers; walk on one thread via smem;
// threefry baked at compile time; FMA orders identical to passing kernels.

#define NN   6
#define EMBD 32
#define H1   64
#define H2   32

// ---------------- compile-time threefry2x32 (partitionable JAX path) ----------------
struct TF2 { unsigned a, b; };

constexpr unsigned rotl_c(unsigned x, int r) { return (x << r) | (x >> (32 - r)); }

constexpr TF2 tf_const(unsigned k0, unsigned k1, unsigned x0, unsigned x1) {
    unsigned ks2 = k0 ^ k1 ^ 0x1BD11BDAu;
    x0 += k0; x1 += k1;
#define TFC(r) { x0 += x1; x1 = rotl_c(x1, r); x1 ^= x0; }
    TFC(13) TFC(15) TFC(26) TFC(6)
    x0 += k1;  x1 += ks2 + 1u;
    TFC(17) TFC(29) TFC(16) TFC(24)
    x0 += ks2; x1 += k0 + 2u;
    TFC(13) TFC(15) TFC(26) TFC(6)
    x0 += k0;  x1 += k1 + 3u;
    TFC(17) TFC(29) TFC(16) TFC(24)
    x0 += k1;  x1 += ks2 + 4u;
    TFC(13) TFC(15) TFC(26) TFC(6)
    x0 += ks2; x1 += k0 + 5u;
#undef TFC
    return TF2{x0, x1};
}

// split(key(42),5)[s] = tf((0,42),(0,s)); bits[j] = o0^o1 of tf(key,(0,j))
constexpr unsigned gbits(unsigned s, unsigned j) {
    TF2 key = tf_const(0u, 42u, 0u, s);
    TF2 o   = tf_const(key.a, key.b, 0u, j);
    return o.a ^ o.b;
}

#define GB(s) gbits(s,0), gbits(s,1), gbits(s,2), gbits(s,3), gbits(s,4), gbits(s,5)
__constant__ unsigned BITS[(NN - 1) * NN] = { GB(0), GB(1), GB(2), GB(3), GB(4) };
#undef GB

// JAX uniform(tiny,1) fp32 -> gumbel. (1-tiny) rounds to 1.0f => u = max(tiny, f+tiny).
__device__ __forceinline__ float gumbel_from_bits(unsigned b) {
    const float tiny = 1.1754943508222875e-38f;
    float f = __uint_as_float((b >> 9) | 0x3f800000u) - 1.0f;
    float u = fmaxf(__fadd_rn(f, tiny), tiny);
    return -logf(-logf(u));
}

#define BARSYNC(id, n) asm volatile("bar.sync %0, %1;" :: "r"(id), "r"(n) : "memory")
#define SHFL(v, l) __shfl_sync(0xffffffffu, (v), (l))

__global__ __launch_bounds__(288, 1)
void node2vec_kernel(const float* __restrict__ x,
                     const float* __restrict__ fc1_w, const float* __restrict__ fc1_b,
                     const float* __restrict__ fc2_w, const float* __restrict__ fc2_b,
                     const float* __restrict__ fc3_w, const float* __restrict__ fc3_b,
                     const float* __restrict__ pw,    const float* __restrict__ pb,
                     float* __restrict__ out) {
    __shared__ float logits[NN][NN];         // raw logits (softmax cancels in argmax)
    __shared__ float g[NN - 1][NN];

    int tid = threadIdx.x;

    if (tid < 192) {
        // ============ ENERGY CHAIN: warp w = node w, barrier-free ============
        int w = tid >> 5;                    // 0..5 = node index
        int l = tid & 31;                    // lane

        // x row w: one element per lane (EMB == warp size)
        float xv = x[w * EMBD + l];

        // register prefetch: w1 columns l and l+32 (feed h1), then w2 column l
        float w1a[EMBD], w1b[EMBD];
        #pragma unroll
        for (int k = 0; k < EMBD; k++) {
            w1a[k] = fc1_w[k * H1 + l];
            w1b[k] = fc1_w[k * H1 + l + 32];
        }
        float b1a = fc1_b[l], b1b = fc1_b[l + 32];
        float b2v = fc2_b[l];
        float w3v = fc3_w[l];
        float b3v = fc3_b[0];

        float w2[H1];
        #pragma unroll
        for (int k = 0; k < H1; k++) w2[k] = fc2_w[k * H2 + l];

        // h1[w][l], h1[w][l+32] = relu(x_row . w1col + b): shuffle-broadcast x,
        // accumulation order k=0..31 (identical to passing kernels).
        float a0 = b1a, a1 = b1b;
        #pragma unroll
        for (int k = 0; k < EMBD; k++) {
            float xk = SHFL(xv, k);
            a0 += xk * w1a[k];
            a1 += xk * w1b[k];
        }
        float ha = fmaxf(a0, 0.0f);          // h1[w][l]
        float hb = fmaxf(a1, 0.0f);          // h1[w][l+32]

        // h2[w][l] via shuffle-broadcast of h1 (4-way split, same order/values):
        float c0 = 0.f, c1 = 0.f, c2 = 0.f, c3 = 0.f;
        #pragma unroll
        for (int k = 0; k < 32; k += 4) {    // k < 32 -> ha lanes
            c0 += SHFL(ha, k)     * w2[k];
            c1 += SHFL(ha, k + 1) * w2[k + 1];
            c2 += SHFL(ha, k + 2) * w2[k + 2];
            c3 += SHFL(ha, k + 3) * w2[k + 3];
        }
        #pragma unroll
        for (int k = 32; k < 64; k += 4) {   // k >= 32 -> hb lanes
            c0 += SHFL(hb, k - 32) * w2[k];
            c1 += SHFL(hb, k - 31) * w2[k + 1];
            c2 += SHFL(hb, k - 30) * w2[k + 2];
            c3 += SHFL(hb, k - 29) * w2[k + 3];
        }
        float rel = fmaxf(b2v + ((c0 + c1) + (c2 + c3)), 0.0f);

        // head: scale by fc3_w[l], butterfly reduce, lane 0 softplus + store
        float p = rel * w3v;
        #pragma unroll
        for (int off = 16; off; off >>= 1)
            p += __shfl_xor_sync(0xffffffffu, p, off);
        if (l == 0) {
            float acc = p + b3v;
            out[w] = fmaxf(acc, 0.0f) + log1pf(expf(-fabsf(acc)));  // softplus
        }
    } else {
        // ============ PATH CHAIN (warps 6-8, bar.sync 2, 96 thr) ============
        int t = tid - 192;

        // fixed endpoints: write early from an otherwise-idle thread
        if (t == 40) { out[NN] = 0.0f; out[2 * NN] = 0.0f; }

        // raw logits = x @ path_fc_w + path_fc_b (36 threads) — LDG-bound.
        // log_softmax skipped: per-row constant cancels in the argmax below.
        if (t < NN * NN) {
            int i = t / NN, j = t % NN;
            float acc = pb[j];
            #pragma unroll
            for (int k = 0; k < EMBD; k++)
                acc += x[i * EMBD + k] * pw[k * NN + j];
            logits[i][j] = acc;
        }

        // gumbels (warp 8, 30 threads): bits are compile-time constants; only
        // two device logf calls remain (bit-identical to the passing kernels).
        if (t >= 64 && t < 64 + (NN - 1) * NN) {
            int u = t - 64;
            g[u / NN][u % NN] = gumbel_from_bits(BITS[u]);
        }
        BARSYNC(2, 96);

        // serial gumbel-max walk (thread 192): 6 parallel LDS per step
        if (t == 0) {
            bool mask[NN];
            mask[0] = false;
            #pragma unroll
            for (int j = 1; j < NN; j++) mask[j] = true;

            int cur = 0;
            #pragma unroll
            for (int step = 0; step < NN - 1; step++) {
                float best = -__int_as_float(0x7f800000);
                int bestj = 0;
                bool have = false;
                #pragma unroll
                for (int j = 0; j < NN; j++) {
                    if (!mask[j]) continue;          // where(mask,.,-inf)+g = -inf
                    float v = logits[cur][j] + g[step][j];
                    if (!have || v > best) { best = v; bestj = j; have = true; }
                }
                cur = bestj;
                mask[bestj] = false;
                out[NN + 1 + step] = (float)bestj;
            }
        }
    }
}

extern "C" void kernel_launch(void* const* d_in, const int* in_sizes, int n_in,
                              void* d_out, int out_size) {
    const float* x     = (const float*)d_in[0];
    // d_in[1] = path (int32, unused by the forward outputs)
    const float* fc1_w = (const float*)d_in[2];
    const float* fc1_b = (const float*)d_in[3];
    const float* fc2_w = (const float*)d_in[4];
    const float* fc2_b = (const float*)d_in[5];
    const float* fc3_w = (const float*)d_in[6];
    const float* fc3_b = (const float*)d_in[7];
    const float* pw    = (const float*)d_in[8];
    const float* pb    = (const float*)d_in[9];
    float* out = (float*)d_out;

    node2vec_kernel<<<1, 288>>>(x, fc1_w, fc1_b, fc2_w, fc2_b,
                                fc3_w, fc3_b, pw, pb, out);
}